// round 12
// baseline (speedup 1.0000x reference)
#include <cuda_runtime.h>
#include <cuda_fp16.h>

// ---------------------------------------------------------------------------
// KNNGaussianBlur: out = GaussianBlur_sigma4_radius12(img[0]) with replicate
// padding. (/max ... *max cancels -> no reduction.)
//
// R12: FUSED, with the R5/R7 failure modes designed out:
//  * V phase = R8's proven vblur shape: thread owns one f4 column, streams 40
//    rows, each input row loaded ONCE per block (R5/R7 had 4x y-redundancy).
//  * V output -> fp16 smem (32KB, half the LDS bytes of fp32).
//  * x-halo via overlapping tiles: block output = 1000px, V span = 1024px
//    (span covers output +-12) -> H phase has NO edge branches; V clamps
//    columns (= exact replicate pad).
//  * H phase = R11's proven f32x2 unit (8px x 2 rows, shared weights); the
//    +12 smem offset makes every window exactly 4 aligned LDS.128 per row.
// DRAM: 402MB (vs 602MB two-pass). New floor: fp32 fma pipe ~76us.
// ---------------------------------------------------------------------------

#define H_IMG 4096
#define W_IMG 4096
#define C_IMG 3
#define RADIUS 12

__device__ constexpr float KW[13] = {
    0.09990835f, 0.09683452f, 0.08816879f, 0.07541476f, 0.06059747f,
    0.04574137f, 0.03243549f, 0.02160670f, 0.01352113f, 0.00794866f,
    0.00438966f, 0.00227733f, 0.00110988f
};

__device__ __forceinline__ unsigned long long pack2(float lo, float hi) {
    unsigned long long r;
    asm("mov.b64 %0, {%1, %2};" : "=l"(r) : "f"(lo), "f"(hi));
    return r;
}
__device__ __forceinline__ void unpack2(unsigned long long v, float& lo, float& hi) {
    asm("mov.b64 {%0, %1}, %2;" : "=f"(lo), "=f"(hi) : "l"(v));
}
__device__ __forceinline__ void fma2(unsigned long long& acc,
                                     unsigned long long a, unsigned long long w) {
    asm("fma.rn.f32x2 %0, %1, %2, %0;" : "+l"(acc) : "l"(a), "l"(w));
}

constexpr int TOUT = 1000;                 // output px per block (x)
constexpr int OH   = 16;                   // output rows per block
constexpr int NBX  = 5;                    // ceil(4096 / 1000)

__global__ __launch_bounds__(256)
void fused_blur_kernel(const float4* __restrict__ in, float* __restrict__ out) {
    // V-blurred span: 16 rows x 1024 px fp16 = 32KB. Row r, half index s
    // holds global x = 1000*bx - 12 + s.
    __shared__ __half vt[OH][1024];

    const int W4  = W_IMG / 4;             // 1024
    const int bx  = blockIdx.x;
    const int y0  = blockIdx.y * OH;
    const int cch = blockIdx.z;
    const int t   = threadIdx.x;

    const float4* inc  = in + (size_t)cch * ((size_t)H_IMG * W4);
    const float*  incf = (const float*)inc;

    // ------------------------- Vertical phase --------------------------
    // Thread t owns f4 column gf4 = 250*bx - 3 + t (span 1024px incl halo).
    // Streams 40 rows (row clamp = replicate pad). OOB columns broadcast the
    // edge pixel (exact: an OOB f4 is entirely outside the image).
    {
        int gf4  = 250 * bx - 3 + t;
        bool inb = (gf4 >= 0) && (gf4 < W4);
        int cadj = gf4 < 0 ? 0 : W_IMG - 1;

        float4 acc[OH];
#pragma unroll
        for (int i = 0; i < OH; ++i) acc[i] = make_float4(0.f, 0.f, 0.f, 0.f);

#pragma unroll
        for (int rr = 0; rr < OH + 2 * RADIUS; ++rr) {
            int row = y0 - RADIUS + rr;
            row = row < 0 ? 0 : (row > H_IMG - 1 ? H_IMG - 1 : row);
            float4 v;
            if (inb) {
                v = __ldg(&inc[(size_t)row * W4 + gf4]);
            } else {
                float s = __ldg(&incf[(size_t)row * W_IMG + cadj]);
                v = make_float4(s, s, s, s);
            }
#pragma unroll
            for (int i = 0; i < OH; ++i) {
                int d = rr - RADIUS - i;           // compile-time per (rr,i)
                if (d >= -RADIUS && d <= RADIUS) {
                    float w = KW[d < 0 ? -d : d];
                    acc[i].x = fmaf(v.x, w, acc[i].x);
                    acc[i].y = fmaf(v.y, w, acc[i].y);
                    acc[i].z = fmaf(v.z, w, acc[i].z);
                    acc[i].w = fmaf(v.w, w, acc[i].w);
                }
            }
        }

#pragma unroll
        for (int i = 0; i < OH; ++i) {
            __half2 lo = __floats2half2_rn(acc[i].x, acc[i].y);
            __half2 hi = __floats2half2_rn(acc[i].z, acc[i].w);
            uint2 pk = make_uint2(*(unsigned*)&lo, *(unsigned*)&hi);
            *(uint2*)&vt[i][4 * t] = pk;           // STS.64, conflict-free
        }
    }

    __syncthreads();

    // ------------------------ Horizontal phase -------------------------
    // Unit = 8 output px x 2 rows (f32x2: lane0=row even, lane1=row odd).
    // Unit (rp, xu): rows y0+2rp(+1), local px lp=8*xu. Window = smem halves
    // [lp, lp+31] per row = exactly 4 aligned LDS.128. 1000 units in an
    // 8x128 grid (xu<125); 4 passes of 256 threads.
    {
        unsigned long long w2[13];
#pragma unroll
        for (int k = 0; k < 13; ++k) w2[k] = pack2(KW[k], KW[k]);

        size_t obase = (size_t)cch * ((size_t)H_IMG * W_IMG);

#pragma unroll
        for (int pass = 0; pass < 4; ++pass) {
            int u  = pass * 256 + t;
            int rp = u >> 7;                       // row-pair 0..7
            int xu = u & 127;                      // x-unit (valid < 125)
            int X0 = TOUT * bx + 8 * xu;           // global first output px
            if (xu < 125 && X0 < W_IMG) {
                int lp = 8 * xu;
                const uint4* s0 = (const uint4*)&vt[2 * rp][lp];
                const uint4* s1 = (const uint4*)&vt[2 * rp + 1][lp];

                unsigned long long acc[8];
#pragma unroll
                for (int p = 0; p < 8; ++p) acc[p] = 0ull;

#pragma unroll
                for (int j = 0; j < 4; ++j) {
                    uint4 q0 = s0[j];
                    uint4 q1 = s1[j];
#pragma unroll
                    for (int h2i = 0; h2i < 4; ++h2i) {
                        unsigned ua = (h2i == 0) ? q0.x : (h2i == 1) ? q0.y
                                    : (h2i == 2) ? q0.z : q0.w;
                        unsigned ub = (h2i == 0) ? q1.x : (h2i == 1) ? q1.y
                                    : (h2i == 2) ? q1.z : q1.w;
                        float2 fa = __half22float2(*(__half2*)&ua);
                        float2 fb = __half22float2(*(__half2*)&ub);
#pragma unroll
                        for (int k = 0; k < 2; ++k) {
                            int m = 8 * j + 2 * h2i + k;   // 0..31, const
                            unsigned long long xv =
                                pack2(k ? fa.y : fa.x, k ? fb.y : fb.x);
#pragma unroll
                            for (int p = 0; p < 8; ++p) {
                                int d = m - RADIUS - p;    // const tap
                                if (d >= -RADIUS && d <= RADIUS)
                                    fma2(acc[p], xv, w2[d < 0 ? -d : d]);
                            }
                        }
                    }
                }

                float lo[8], hi[8];
#pragma unroll
                for (int p = 0; p < 8; ++p) unpack2(acc[p], lo[p], hi[p]);

                float* o0 = out + obase + (size_t)(y0 + 2 * rp) * W_IMG + X0;
                float* o1 = o0 + W_IMG;
                *(float4*)o0       = make_float4(lo[0], lo[1], lo[2], lo[3]);
                *(float4*)(o0 + 4) = make_float4(lo[4], lo[5], lo[6], lo[7]);
                *(float4*)o1       = make_float4(hi[0], hi[1], hi[2], hi[3]);
                *(float4*)(o1 + 4) = make_float4(hi[4], hi[5], hi[6], hi[7]);
            }
        }
    }
}

// ------------------------------ entry point --------------------------------
extern "C" void kernel_launch(void* const* d_in, const int* in_sizes, int n_in,
                              void* d_out, int out_size) {
    const float* img = (const float*)d_in[0];      // [1,3,4096,4096] fp32
    float* out = (float*)d_out;                    // [3,4096,4096] fp32

    dim3 grid(NBX, H_IMG / OH, C_IMG);             // (5, 256, 3)
    fused_blur_kernel<<<grid, 256>>>((const float4*)img, out);
}

// round 14
// speedup vs baseline: 1.4786x; 1.4786x over previous
#include <cuda_runtime.h>
#include <cuda_fp16.h>

// ---------------------------------------------------------------------------
// KNNGaussianBlur: out = GaussianBlur_sigma4_radius12(img[0]) with replicate
// padding. (/max ... *max cancels -> no reduction.)
//
// R14 = R11 (best passing: two-pass, fp16 scratch, f32x2 hblur, 118.8us)
// with ONE change: vblur also uses packed fma.rn.f32x2 (float4 = 2 u64
// lanes, 13 shared (w,w) weight pairs). vblur FMA warp-instrs halve.
// Evidence vblur is issue-sensitive: R10 (more instrs, same bytes) made it
// slower. Concurrency (R13) is closed: streams allocate device memory
// (rule violation) and the leaked timing showed 134us anyway.
// ---------------------------------------------------------------------------

#define H_IMG 4096
#define W_IMG 4096
#define C_IMG 3
#define RADIUS 12

// 100.7 MB fp16 scratch (device global: allocation in kernel_launch is banned).
__device__ __half g_scratch[(size_t)C_IMG * H_IMG * W_IMG];

// 13 unique weights of the 25-tap Gaussian (sigma=4), normalized.
__device__ constexpr float KW[13] = {
    0.09990835f, 0.09683452f, 0.08816879f, 0.07541476f, 0.06059747f,
    0.04574137f, 0.03243549f, 0.02160670f, 0.01352113f, 0.00794866f,
    0.00438966f, 0.00227733f, 0.00110988f
};

__device__ __forceinline__ unsigned long long pack2(float lo, float hi) {
    unsigned long long r;
    asm("mov.b64 %0, {%1, %2};" : "=l"(r) : "f"(lo), "f"(hi));
    return r;
}
__device__ __forceinline__ void unpack2(unsigned long long v, float& lo, float& hi) {
    asm("mov.b64 {%0, %1}, %2;" : "=f"(lo), "=f"(hi) : "l"(v));
}
__device__ __forceinline__ void fma2(unsigned long long& acc,
                                     unsigned long long a, unsigned long long w) {
    asm("fma.rn.f32x2 %0, %1, %2, %0;" : "+l"(acc) : "l"(a), "l"(w));
}

// ------------------------------ Vertical pass ------------------------------
// Thread = one f4 column x 16 output rows, streams 40 rows (row clamp =
// replicate pad). NEW: accumulators are f32x2 pairs (aLo = px {x,y},
// aHi = px {z,w}); each fma.rn.f32x2 retires 2 FMAs with a shared weight.
constexpr int VROWS = 16;

__global__ __launch_bounds__(128)
void vblur_kernel(const float* __restrict__ in) {
    const int W4 = W_IMG / 4;                      // 1024
    int col4 = blockIdx.x * 128 + threadIdx.x;     // 0..1023
    int y0   = blockIdx.y * VROWS;
    int cch  = blockIdx.z;

    const float* incf = in + (size_t)cch * ((size_t)H_IMG * W_IMG);
    const ulonglong2* inc = (const ulonglong2*)incf;
    __half* outc = g_scratch + (size_t)cch * ((size_t)H_IMG * W_IMG);

    unsigned long long w2[13];
#pragma unroll
    for (int k = 0; k < 13; ++k) w2[k] = pack2(KW[k], KW[k]);

    unsigned long long aLo[VROWS], aHi[VROWS];
#pragma unroll
    for (int i = 0; i < VROWS; ++i) { aLo[i] = 0ull; aHi[i] = 0ull; }

#pragma unroll
    for (int rr = 0; rr < VROWS + 2 * RADIUS; ++rr) {
        int row = y0 - RADIUS + rr;
        row = row < 0 ? 0 : (row > H_IMG - 1 ? H_IMG - 1 : row);
        ulonglong2 v = __ldg(&inc[(size_t)row * W4 + col4]);
#pragma unroll
        for (int i = 0; i < VROWS; ++i) {
            int d = rr - RADIUS - i;               // compile-time per (rr,i)
            if (d >= -RADIUS && d <= RADIUS) {
                unsigned long long w = w2[d < 0 ? -d : d];
                fma2(aLo[i], v.x, w);
                fma2(aHi[i], v.y, w);
            }
        }
    }

#pragma unroll
    for (int i = 0; i < VROWS; ++i) {
        float ax, ay, az, aw;
        unpack2(aLo[i], ax, ay);
        unpack2(aHi[i], az, aw);
        __half2 lo = __floats2half2_rn(ax, ay);
        __half2 hi = __floats2half2_rn(az, aw);
        uint2 pk = make_uint2(*(unsigned*)&lo, *(unsigned*)&hi);
        *(uint2*)(outc + (size_t)(y0 + i) * W_IMG + 4 * (size_t)col4) = pk;
    }
}

// ----------------------------- Horizontal pass -----------------------------
// R11's f32x2 row-pair kernel (unchanged): block = one row pair; lane owns a
// half8 slot (8 consecutive px) in both rows; 5 coalesced 16B loads per row;
// acc lanes = (row0,row1) share one weight per fma.rn.f32x2. OOB slots
// broadcast the edge pixel (exact replicate padding since W = 4096 = 512*8).
__global__ __launch_bounds__(256)
void hblur_kernel(float* __restrict__ out) {
    int rp   = blockIdx.x;                         // row pair 0..2047
    int cch  = blockIdx.y;
    int w    = threadIdx.x >> 5;
    int lane = threadIdx.x & 31;

    size_t r0base = ((size_t)cch * H_IMG + 2 * (size_t)rp) * W_IMG;
    const __half* inr0 = g_scratch + r0base;
    const __half* inr1 = inr0 + W_IMG;
    const uint4*  inA  = (const uint4*)inr0;       // 512 slots of 8 halves
    const uint4*  inB  = (const uint4*)inr1;

    unsigned long long w2[13];
#pragma unroll
    for (int k = 0; k < 13; ++k) w2[k] = pack2(KW[k], KW[k]);

#pragma unroll
    for (int g = 0; g < 2; ++g) {
        int b8   = 64 * w + 32 * g + lane;         // owned slot 0..511
        int base = 8 * b8;                         // first output px

        unsigned long long acc[8];
#pragma unroll
        for (int p = 0; p < 8; ++p) acc[p] = 0ull;

#pragma unroll
        for (int j = 0; j < 5; ++j) {
            int s = b8 - 2 + j;
            uint4 q0, q1;
            if (s >= 0 && s < W_IMG / 8) {
                q0 = __ldg(&inA[s]);
                q1 = __ldg(&inB[s]);
            } else {
                int ec = s < 0 ? 0 : W_IMG - 1;
                unsigned h0 = (unsigned)__half_as_ushort(__ldg(&inr0[ec]));
                unsigned h1 = (unsigned)__half_as_ushort(__ldg(&inr1[ec]));
                h0 |= h0 << 16;  h1 |= h1 << 16;
                q0 = make_uint4(h0, h0, h0, h0);
                q1 = make_uint4(h1, h1, h1, h1);
            }
#pragma unroll
            for (int h2i = 0; h2i < 4; ++h2i) {
                unsigned ua = (h2i == 0) ? q0.x : (h2i == 1) ? q0.y
                            : (h2i == 2) ? q0.z : q0.w;
                unsigned ub = (h2i == 0) ? q1.x : (h2i == 1) ? q1.y
                            : (h2i == 2) ? q1.z : q1.w;
                float2 fa = __half22float2(*(__half2*)&ua);   // row0: x, x+1
                float2 fb = __half22float2(*(__half2*)&ub);   // row1: x, x+1
#pragma unroll
                for (int k = 0; k < 2; ++k) {
                    int m = 8 * j + 2 * h2i + k;   // 0..39, compile-time
                    unsigned long long xv =
                        pack2(k ? fa.y : fa.x, k ? fb.y : fb.x);
#pragma unroll
                    for (int p = 0; p < 8; ++p) {
                        int d = m - 16 - p;        // compile-time tap offset
                        if (d >= -RADIUS && d <= RADIUS)
                            fma2(acc[p], xv, w2[d < 0 ? -d : d]);
                    }
                }
            }
        }

        float lo[8], hi[8];
#pragma unroll
        for (int p = 0; p < 8; ++p) unpack2(acc[p], lo[p], hi[p]);

        float* o0 = out + r0base + base;
        float* o1 = o0 + W_IMG;
        *(float4*)o0       = make_float4(lo[0], lo[1], lo[2], lo[3]);
        *(float4*)(o0 + 4) = make_float4(lo[4], lo[5], lo[6], lo[7]);
        *(float4*)o1       = make_float4(hi[0], hi[1], hi[2], hi[3]);
        *(float4*)(o1 + 4) = make_float4(hi[4], hi[5], hi[6], hi[7]);
    }
}

// ------------------------------ entry point --------------------------------
extern "C" void kernel_launch(void* const* d_in, const int* in_sizes, int n_in,
                              void* d_out, int out_size) {
    const float* img = (const float*)d_in[0];      // [1,3,4096,4096] fp32
    float* out = (float*)d_out;                    // [3,4096,4096] fp32

    dim3 vgrid(W_IMG / 4 / 128, H_IMG / VROWS, C_IMG);   // (8, 256, 3)
    vblur_kernel<<<vgrid, 128>>>(img);

    dim3 hgrid(H_IMG / 2, C_IMG);                        // (2048, 3)
    hblur_kernel<<<hgrid, 256>>>(out);
}

// round 15
// speedup vs baseline: 1.5120x; 1.0226x over previous
#include <cuda_runtime.h>
#include <cuda_fp16.h>

// ---------------------------------------------------------------------------
// KNNGaussianBlur: out = GaussianBlur_sigma4_radius12(img[0]) with replicate
// padding. (/max ... *max cancels -> no reduction.)
//
// R15 = R14 (two-pass, fp16 scratch, f32x2 in both passes, 113.1us) with a
// ROW-PAIR-INTERLEAVED scratch layout: scratch halves are ordered
// (r0[x], r1[x], r0[x+1], r1[x+1], ...) per row pair. hblur's loaded half2
// IS the (row0,row1) f32x2 operand after one convert -> the 40 cross-row
// pack2 movs per group vanish and the window becomes one contiguous 128B
// run (8 LDG.128 vs 10). vblur stores 8 STG.128 vs 16 STG.64.
// ---------------------------------------------------------------------------

#define H_IMG 4096
#define W_IMG 4096
#define C_IMG 3
#define RADIUS 12

// 100.7 MB fp16 scratch, layout [C][H/2][W][2]: for row pair rp, position x:
// scratch[((c*2048+rp)*4096 + x)*2 + r] = vblur(row 2rp+r, x).
__device__ __half g_scratch[(size_t)C_IMG * H_IMG * W_IMG];

// 13 unique weights of the 25-tap Gaussian (sigma=4), normalized.
__device__ constexpr float KW[13] = {
    0.09990835f, 0.09683452f, 0.08816879f, 0.07541476f, 0.06059747f,
    0.04574137f, 0.03243549f, 0.02160670f, 0.01352113f, 0.00794866f,
    0.00438966f, 0.00227733f, 0.00110988f
};

__device__ __forceinline__ unsigned long long pack2(float lo, float hi) {
    unsigned long long r;
    asm("mov.b64 %0, {%1, %2};" : "=l"(r) : "f"(lo), "f"(hi));
    return r;
}
__device__ __forceinline__ void unpack2(unsigned long long v, float& lo, float& hi) {
    asm("mov.b64 {%0, %1}, %2;" : "=f"(lo), "=f"(hi) : "l"(v));
}
__device__ __forceinline__ void fma2(unsigned long long& acc,
                                     unsigned long long a, unsigned long long w) {
    asm("fma.rn.f32x2 %0, %1, %2, %0;" : "+l"(acc) : "l"(a), "l"(w));
}

// ------------------------------ Vertical pass ------------------------------
// Thread = one f4 column x 16 output rows (8 row pairs), streams 40 rows
// (row clamp = replicate pad). f32x2 accumulators (aLo = px{x,y}, aHi =
// px{z,w}). Store: row-pair interleave, one STG.128 per pair, coalesced.
constexpr int VROWS = 16;

__global__ __launch_bounds__(128)
void vblur_kernel(const float* __restrict__ in) {
    const int W4 = W_IMG / 4;                      // 1024
    int col4 = blockIdx.x * 128 + threadIdx.x;     // 0..1023
    int y0   = blockIdx.y * VROWS;
    int cch  = blockIdx.z;

    const float* incf = in + (size_t)cch * ((size_t)H_IMG * W_IMG);
    const ulonglong2* inc = (const ulonglong2*)incf;
    __half* outc = g_scratch + (size_t)cch * ((size_t)H_IMG * W_IMG);

    unsigned long long w2[13];
#pragma unroll
    for (int k = 0; k < 13; ++k) w2[k] = pack2(KW[k], KW[k]);

    unsigned long long aLo[VROWS], aHi[VROWS];
#pragma unroll
    for (int i = 0; i < VROWS; ++i) { aLo[i] = 0ull; aHi[i] = 0ull; }

#pragma unroll
    for (int rr = 0; rr < VROWS + 2 * RADIUS; ++rr) {
        int row = y0 - RADIUS + rr;
        row = row < 0 ? 0 : (row > H_IMG - 1 ? H_IMG - 1 : row);
        ulonglong2 v = __ldg(&inc[(size_t)row * W4 + col4]);
#pragma unroll
        for (int i = 0; i < VROWS; ++i) {
            int d = rr - RADIUS - i;               // compile-time per (rr,i)
            if (d >= -RADIUS && d <= RADIUS) {
                unsigned long long w = w2[d < 0 ? -d : d];
                fma2(aLo[i], v.x, w);
                fma2(aHi[i], v.y, w);
            }
        }
    }

    // Interleaved store: pair i = rows (y0+2i, y0+2i+1). 8 halves per pair:
    // (r0.x, r1.x, r0.y, r1.y, r0.z, r1.z, r0.w, r1.w) = one uint4.
#pragma unroll
    for (int i = 0; i < VROWS / 2; ++i) {
        float a0x, a0y, a0z, a0w, a1x, a1y, a1z, a1w;
        unpack2(aLo[2 * i],     a0x, a0y); unpack2(aHi[2 * i],     a0z, a0w);
        unpack2(aLo[2 * i + 1], a1x, a1y); unpack2(aHi[2 * i + 1], a1z, a1w);
        __half2 p0 = __floats2half2_rn(a0x, a1x);
        __half2 p1 = __floats2half2_rn(a0y, a1y);
        __half2 p2 = __floats2half2_rn(a0z, a1z);
        __half2 p3 = __floats2half2_rn(a0w, a1w);
        uint4 pk = make_uint4(*(unsigned*)&p0, *(unsigned*)&p1,
                              *(unsigned*)&p2, *(unsigned*)&p3);
        size_t rp = (size_t)(y0 / 2 + i);
        *(uint4*)(outc + (rp * W_IMG + 4 * (size_t)col4) * 2) = pk;
    }
}

// ----------------------------- Horizontal pass -----------------------------
// Block = one row pair; thread owns 2 groups of 8 px x 2 rows. Window for a
// group = x in [base-12, base+19] = 8 contiguous LDG.128 (16B aligned).
// Every loaded half2 converts straight into the (row0,row1) f32x2 operand.
// OOB uint4s broadcast the edge (r0,r1) pair (exact replicate padding).
__global__ __launch_bounds__(256)
void hblur_kernel(float* __restrict__ out) {
    int rp   = blockIdx.x;                         // row pair 0..2047
    int cch  = blockIdx.y;
    int w    = threadIdx.x >> 5;
    int lane = threadIdx.x & 31;

    const __half* inh = g_scratch
        + ((size_t)cch * (H_IMG / 2) + rp) * ((size_t)W_IMG * 2);
    const uint4* in4 = (const uint4*)inh;          // u covers x = 4u..4u+3

    unsigned long long w2[13];
#pragma unroll
    for (int k = 0; k < 13; ++k) w2[k] = pack2(KW[k], KW[k]);

#pragma unroll
    for (int g = 0; g < 2; ++g) {
        int b8   = 64 * w + 32 * g + lane;         // owned 8px slot 0..511
        int base = 8 * b8;                         // first output px

        unsigned long long acc[8];
#pragma unroll
        for (int p = 0; p < 8; ++p) acc[p] = 0ull;

#pragma unroll
        for (int j = 0; j < 8; ++j) {
            int u = 2 * b8 - 3 + j;                // x = 4u..4u+3
            uint4 q;
            if (u >= 0 && u < W_IMG / 4) {
                q = __ldg(&in4[u]);
            } else {
                // whole uint4 OOB -> broadcast edge (r0,r1) pair
                unsigned pe = __ldg((const unsigned*)inh
                                    + (u < 0 ? 0 : W_IMG - 1));
                q = make_uint4(pe, pe, pe, pe);
            }
#pragma unroll
            for (int h = 0; h < 4; ++h) {
                unsigned uq = (h == 0) ? q.x : (h == 1) ? q.y
                            : (h == 2) ? q.z : q.w;
                float2 f = __half22float2(*(__half2*)&uq);  // (r0[x], r1[x])
                unsigned long long xv = pack2(f.x, f.y);
                int m = 4 * j + h;                 // x - (base-12), 0..31
#pragma unroll
                for (int p = 0; p < 8; ++p) {
                    int d = m - RADIUS - p;        // compile-time tap offset
                    if (d >= -RADIUS && d <= RADIUS)
                        fma2(acc[p], xv, w2[d < 0 ? -d : d]);
                }
            }
        }

        float lo[8], hi[8];
#pragma unroll
        for (int p = 0; p < 8; ++p) unpack2(acc[p], lo[p], hi[p]);

        float* o0 = out + ((size_t)cch * H_IMG + 2 * (size_t)rp) * W_IMG + base;
        float* o1 = o0 + W_IMG;
        *(float4*)o0       = make_float4(lo[0], lo[1], lo[2], lo[3]);
        *(float4*)(o0 + 4) = make_float4(lo[4], lo[5], lo[6], lo[7]);
        *(float4*)o1       = make_float4(hi[0], hi[1], hi[2], hi[3]);
        *(float4*)(o1 + 4) = make_float4(hi[4], hi[5], hi[6], hi[7]);
    }
}

// ------------------------------ entry point --------------------------------
extern "C" void kernel_launch(void* const* d_in, const int* in_sizes, int n_in,
                              void* d_out, int out_size) {
    const float* img = (const float*)d_in[0];      // [1,3,4096,4096] fp32
    float* out = (float*)d_out;                    // [3,4096,4096] fp32

    dim3 vgrid(W_IMG / 4 / 128, H_IMG / VROWS, C_IMG);   // (8, 256, 3)
    vblur_kernel<<<vgrid, 128>>>(img);

    dim3 hgrid(H_IMG / 2, C_IMG);                        // (2048, 3)
    hblur_kernel<<<hgrid, 256>>>(out);
}